// round 3
// baseline (speedup 1.0000x reference)
#include <cuda_runtime.h>
#include <math.h>

#define BB 64
#define TT 512
#define II 1024
#define HH 1024
#define GG 4096              // 4*H
#define MM (BB*TT)           // 32768
#define KSPLIT 4
#define NBLK 256             // persistent kernel grid size

// Scratch (device globals: allocation-free per harness rules)
__device__ float g_xproj[(size_t)MM * GG];          // [B*T, 4H]  512 MB
__device__ float g_hbuf [(size_t)MM * HH];          // [B, T, H]  128 MB (layer ping)
__device__ float g_h    [BB * HH];                  // current h
__device__ float g_part [(size_t)KSPLIT * BB * GG]; // split-K partials, 4 MB

// Software grid barrier state (zero-initialized)
__device__ unsigned g_bar_count;
__device__ volatile unsigned g_bar_gen;

__device__ __forceinline__ void grid_barrier()
{
    __syncthreads();
    if (threadIdx.x == 0) {
        unsigned gen = g_bar_gen;
        __threadfence();                       // release: block's prior writes
        unsigned prev = atomicAdd(&g_bar_count, 1u);
        if (prev == NBLK - 1) {
            atomicExch(&g_bar_count, 0u);
            __threadfence();
            g_bar_gen = gen + 1;               // release all
        } else {
            while (g_bar_gen == gen) { }       // spin (L2 poll)
            __threadfence();                   // acquire
        }
    }
    __syncthreads();
}

// ---------------------------------------------------------------------------
// Big input-projection GEMM:
//   xproj[m, n] = sum_k A[m,k] * W[n,k] + bih[n] + bhh[n]
// A: [M=32768, K=1024] row-major, W: [4096, 1024] row-major (NT gemm).
// Tile 128x128x8, 256 threads, 8x8 per-thread register tile.
// ---------------------------------------------------------------------------
__global__ void __launch_bounds__(256) gemm_bias_kernel(
    const float* __restrict__ Ain,
    const float* __restrict__ W,
    const float* __restrict__ bih,
    const float* __restrict__ bhh,
    int in_is_hbuf)
{
    __shared__ float As[8][128];
    __shared__ float Bs[8][128];

    const float* A = in_is_hbuf ? (const float*)g_hbuf : Ain;

    const int tid = threadIdx.x;
    const int bn  = blockIdx.x;       // 0..31  (N tiles)
    const int bm  = blockIdx.y;       // 0..255 (M tiles)

    const int lr = tid >> 1;          // 0..127 row within tile
    const int lc = (tid & 1) * 4;     // 0 or 4 (k offset)
    const int tm = (tid >> 4) * 8;    // 0..120
    const int tn = (tid & 15) * 8;    // 0..120

    const float* Ag = A + (size_t)(bm * 128 + lr) * II + lc;
    const float* Wg = W + (size_t)(bn * 128 + lr) * II + lc;

    float acc[8][8] = {};

    for (int k0 = 0; k0 < II; k0 += 8) {
        float4 a4 = *(const float4*)(Ag + k0);
        float4 b4 = *(const float4*)(Wg + k0);
        __syncthreads();
        As[lc+0][lr] = a4.x; As[lc+1][lr] = a4.y; As[lc+2][lr] = a4.z; As[lc+3][lr] = a4.w;
        Bs[lc+0][lr] = b4.x; Bs[lc+1][lr] = b4.y; Bs[lc+2][lr] = b4.z; Bs[lc+3][lr] = b4.w;
        __syncthreads();
        #pragma unroll
        for (int kk = 0; kk < 8; kk++) {
            float ar[8], br[8];
            #pragma unroll
            for (int i = 0; i < 8; i++) ar[i] = As[kk][tm + i];
            #pragma unroll
            for (int j = 0; j < 8; j++) br[j] = Bs[kk][tn + j];
            #pragma unroll
            for (int i = 0; i < 8; i++)
                #pragma unroll
                for (int j = 0; j < 8; j++)
                    acc[i][j] = fmaf(ar[i], br[j], acc[i][j]);
        }
    }

    float bs[8];
    #pragma unroll
    for (int j = 0; j < 8; j++) {
        int n = bn * 128 + tn + j;
        bs[j] = bih[n] + bhh[n];
    }
    #pragma unroll
    for (int i = 0; i < 8; i++) {
        size_t m = (size_t)(bm * 128 + tm + i);
        float* Crow = g_xproj + m * GG + bn * 128 + tn;
        float4 v0 = make_float4(acc[i][0]+bs[0], acc[i][1]+bs[1], acc[i][2]+bs[2], acc[i][3]+bs[3]);
        float4 v1 = make_float4(acc[i][4]+bs[4], acc[i][5]+bs[5], acc[i][6]+bs[6], acc[i][7]+bs[7]);
        *(float4*)(Crow)     = v0;
        *(float4*)(Crow + 4) = v1;
    }
}

// ---------------------------------------------------------------------------
// Persistent recurrence kernel: loops over all T timesteps for one layer.
// Phase A (t>0): split-K GEMM  part[s][m][n] = sum_{k in chunk s} h[m,k]*Whh[n,k]
//   block = (bn = blockIdx.x & 63, ks = blockIdx.x >> 6); 64x64 tile, 4x4/thread.
// Phase B: elementwise gates; 1 element per thread; c kept in a register.
// Two grid barriers per step.
// ---------------------------------------------------------------------------
__global__ void __launch_bounds__(256, 2) rec_persist_kernel(
    const float* __restrict__ Whh,
    float* __restrict__ out_ext,
    int out_is_hbuf)
{
    __shared__ float As[8][64];
    __shared__ float Bs[8][64];

    const int tid = threadIdx.x;
    const int bn  = blockIdx.x & 63;       // n tile 0..63
    const int ks  = blockIdx.x >> 6;       // k split 0..3
    const int kbase = ks * (HH / KSPLIT);

    // GEMM thread mapping
    const int lrow = (tid & 127) >> 1;     // 0..63
    const int lk   = (tid & 1) * 4;        // 0 or 4
    const int tm   = (tid >> 4) * 4;       // 0..60
    const int tn   = (tid & 15) * 4;       // 0..60

    const float* Ag = g_h + (size_t)lrow * HH + kbase + lk;
    const float* Wg = Whh + (size_t)(bn * 64 + lrow) * HH + kbase + lk;
    float* Pout = g_part + (size_t)ks * BB * GG + (size_t)bn * 64 + tn;

    // Elementwise thread mapping (one element per thread, fixed for all t)
    const int eidx = blockIdx.x * 256 + tid;  // 0..65535
    const int b = eidx >> 10;
    const int j = eidx & 1023;
    const float* xp_base = g_xproj + (size_t)b * TT * GG + j;
    float* out = out_is_hbuf ? g_hbuf : out_ext;
    float* out_base = out + (size_t)b * TT * HH + j;

    float creg = 0.0f;                      // cell state lives in a register

    for (int t = 0; t < TT; t++) {
        // ---- Phase A: recurrent GEMM partials (skip at t=0: h == 0) ----
        if (t > 0) {
            float acc[4][4] = {};
            for (int k0 = 0; k0 < HH / KSPLIT; k0 += 8) {
                float4 v;
                if (tid < 128) v = *(const float4*)(Ag + k0);
                else           v = *(const float4*)(Wg + k0);
                __syncthreads();
                if (tid < 128) {
                    As[lk+0][lrow] = v.x; As[lk+1][lrow] = v.y;
                    As[lk+2][lrow] = v.z; As[lk+3][lrow] = v.w;
                } else {
                    Bs[lk+0][lrow] = v.x; Bs[lk+1][lrow] = v.y;
                    Bs[lk+2][lrow] = v.z; Bs[lk+3][lrow] = v.w;
                }
                __syncthreads();
                #pragma unroll
                for (int kk = 0; kk < 8; kk++) {
                    float ar[4], br[4];
                    #pragma unroll
                    for (int i = 0; i < 4; i++) ar[i] = As[kk][tm + i];
                    #pragma unroll
                    for (int jj = 0; jj < 4; jj++) br[jj] = Bs[kk][tn + jj];
                    #pragma unroll
                    for (int i = 0; i < 4; i++)
                        #pragma unroll
                        for (int jj = 0; jj < 4; jj++)
                            acc[i][jj] = fmaf(ar[i], br[jj], acc[i][jj]);
                }
            }
            #pragma unroll
            for (int i = 0; i < 4; i++) {
                float4 v = make_float4(acc[i][0], acc[i][1], acc[i][2], acc[i][3]);
                *(float4*)(Pout + (size_t)(tm + i) * GG) = v;
            }
        }

        grid_barrier();   // partials visible

        // ---- Phase B: elementwise LSTM update ----
        {
            const float* xp = xp_base + (size_t)t * GG;
            float gi = xp[0];
            float gf = xp[HH];
            float gg = xp[2 * HH];
            float go = xp[3 * HH];

            if (t > 0) {
                size_t pb = (size_t)b * GG + j;
                #pragma unroll
                for (int s = 0; s < KSPLIT; s++) {
                    const float* P = g_part + (size_t)s * BB * GG + pb;
                    gi += P[0];
                    gf += P[HH];
                    gg += P[2 * HH];
                    go += P[3 * HH];
                }
            }

            float i_g = 1.f / (1.f + expf(-gi));
            float f_g = 1.f / (1.f + expf(-gf));
            float g_g = tanhf(gg);
            float o_g = 1.f / (1.f + expf(-go));

            creg = f_g * creg + i_g * g_g;
            float h = o_g * tanhf(creg);

            g_h[eidx] = h;
            out_base[(size_t)t * HH] = h;
        }

        grid_barrier();   // h visible before next step's GEMM
    }
}

// ---------------------------------------------------------------------------
extern "C" void kernel_launch(void* const* d_in, const int* in_sizes, int n_in,
                              void* d_out, int out_size)
{
    const float* x   = (const float*)d_in[0];   // [B, T, I]
    const float* Wih = (const float*)d_in[1];   // [L, 4H, I]
    const float* Whh = (const float*)d_in[2];   // [L, 4H, H]
    const float* bih = (const float*)d_in[3];   // [L, 4H]
    const float* bhh = (const float*)d_in[4];   // [L, 4H]
    float* out = (float*)d_out;                 // [B, T, H]

    for (int l = 0; l < 3; l++) {
        const float* Wih_l = Wih + (size_t)l * GG * II;
        const float* Whh_l = Whh + (size_t)l * GG * HH;
        const float* bih_l = bih + (size_t)l * GG;
        const float* bhh_l = bhh + (size_t)l * GG;

        int in_is_hbuf  = (l != 0);
        int out_is_hbuf = (l != 2);

        dim3 g1(GG / 128, MM / 128);   // (32, 256)
        gemm_bias_kernel<<<g1, 256>>>(x, Wih_l, bih_l, bhh_l, in_is_hbuf);

        rec_persist_kernel<<<NBLK, 256>>>(Whh_l, out, out_is_hbuf);
    }
}

// round 4
// speedup vs baseline: 1.7981x; 1.7981x over previous
#include <cuda_runtime.h>
#include <math.h>
#include <stdint.h>

#define BB 64
#define TT 512
#define II 1024
#define HH 1024
#define GG 4096              // 4*H
#define MM (BB*TT)           // 32768
#define KSPLIT 4
#define NBLK 256             // persistent kernel grid size

// Scratch (device globals: allocation-free per harness rules)
__device__ float g_xproj[(size_t)MM * GG];          // [B*T, 4H]  512 MB
__device__ float g_hbuf [(size_t)MM * HH];          // [B, T, H]  128 MB
__device__ float g_h    [BB * HH];                  // current h
__device__ float g_part [(size_t)KSPLIT * BB * GG]; // split-K partials, 4 MB

// Software grid barrier state (zero-initialized)
__device__ unsigned g_bar_count;
__device__ volatile unsigned g_bar_gen;

__device__ __forceinline__ void grid_barrier()
{
    __syncthreads();
    if (threadIdx.x == 0) {
        unsigned gen = g_bar_gen;
        __threadfence();
        unsigned prev = atomicAdd(&g_bar_count, 1u);
        if (prev == NBLK - 1) {
            atomicExch(&g_bar_count, 0u);
            __threadfence();
            g_bar_gen = gen + 1;
        } else {
            while (g_bar_gen == gen) { }
            __threadfence();
        }
    }
    __syncthreads();
}

// ---------------------------------------------------------------------------
// tf32 helpers
// ---------------------------------------------------------------------------
__device__ __forceinline__ uint32_t f2tf(float f)
{
    uint32_t u;
    asm("cvt.rna.tf32.f32 %0, %1;" : "=r"(u) : "f"(f));
    return u;
}

__device__ __forceinline__ void mma_tf32(float* d,
    uint32_t a0, uint32_t a1, uint32_t a2, uint32_t a3,
    uint32_t b0, uint32_t b1)
{
    asm("mma.sync.aligned.m16n8k8.row.col.f32.tf32.tf32.f32 "
        "{%0,%1,%2,%3}, {%4,%5,%6,%7}, {%8,%9}, {%0,%1,%2,%3};"
        : "+f"(d[0]), "+f"(d[1]), "+f"(d[2]), "+f"(d[3])
        : "r"(a0), "r"(a1), "r"(a2), "r"(a3), "r"(b0), "r"(b1));
}

// ---------------------------------------------------------------------------
// Input-projection GEMM (tf32 tensor cores):
//   xproj[m,n] = sum_k A[m,k]*W[n,k] + bih[n] + bhh[n]
// Tile 128x128, k-chunks of 32, double-buffered SMEM (tf32-packed, stride 36
// words -> conflict-free fragment loads). 8 warps in 2(m)x4(n), warp tile 64x32.
// ---------------------------------------------------------------------------
#define KC 32
#define ASTR 36

__global__ void __launch_bounds__(256, 2) gemm_bias_tc_kernel(
    const float* __restrict__ Ain,
    const float* __restrict__ W,
    const float* __restrict__ bih,
    const float* __restrict__ bhh,
    int in_is_hbuf)
{
    extern __shared__ uint32_t smw[];
    uint32_t* As = smw;                      // [2][128][36]
    uint32_t* Bs = smw + 2 * 128 * ASTR;     // [2][128][36]

    const float* A = in_is_hbuf ? (const float*)g_hbuf : Ain;

    const int tid  = threadIdx.x;
    const int bn   = blockIdx.x;             // 0..31
    const int bm   = blockIdx.y;             // 0..255
    const int lane = tid & 31, wid = tid >> 5;
    const int g    = lane >> 2, tg = lane & 3;
    const int wm   = wid >> 2;               // 0..1
    const int wn   = wid & 3;                // 0..3
    const int mW   = wm * 64, nW = wn * 32;

    // staging map: row sm, k-half kh
    const int sm = tid & 127;
    const int kh = tid >> 7;                 // 0/1

    const float* Ag = A + (size_t)(bm * 128 + sm) * II;
    const float* Wg = W + (size_t)(bn * 128 + sm) * II;

    float acc[4][4][4];
    #pragma unroll
    for (int mt = 0; mt < 4; mt++)
        #pragma unroll
        for (int nt = 0; nt < 4; nt++)
            #pragma unroll
            for (int e = 0; e < 4; e++) acc[mt][nt][e] = 0.f;

    // bias registers (per thread: 4 ntiles x 2 cols)
    float bb[4][2];
    #pragma unroll
    for (int nt = 0; nt < 4; nt++)
        #pragma unroll
        for (int e = 0; e < 2; e++) {
            int n = bn * 128 + nW + nt * 8 + 2 * tg + e;
            bb[nt][e] = bih[n] + bhh[n];
        }

    float4 ra[4], rb[4];
    // prologue: load chunk 0
    #pragma unroll
    for (int q = 0; q < 4; q++) {
        ra[q] = *(const float4*)(Ag + 16 * kh + 4 * q);
        rb[q] = *(const float4*)(Wg + 16 * kh + 4 * q);
    }
    {
        uint32_t* Ad = As;
        uint32_t* Bd = Bs;
        #pragma unroll
        for (int q = 0; q < 4; q++) {
            int k = 16 * kh + 4 * q;
            uint4 ua = make_uint4(f2tf(ra[q].x), f2tf(ra[q].y), f2tf(ra[q].z), f2tf(ra[q].w));
            uint4 ub = make_uint4(f2tf(rb[q].x), f2tf(rb[q].y), f2tf(rb[q].z), f2tf(rb[q].w));
            *(uint4*)(Ad + sm * ASTR + k) = ua;
            *(uint4*)(Bd + sm * ASTR + k) = ub;
        }
    }
    __syncthreads();

    int buf = 0;
    for (int k0 = 0; k0 < II; k0 += KC) {
        const bool more = (k0 + KC) < II;
        if (more) {
            #pragma unroll
            for (int q = 0; q < 4; q++) {
                ra[q] = *(const float4*)(Ag + k0 + KC + 16 * kh + 4 * q);
                rb[q] = *(const float4*)(Wg + k0 + KC + 16 * kh + 4 * q);
            }
        }

        const uint32_t* Ab = As + buf * 128 * ASTR;
        const uint32_t* Bbuf = Bs + buf * 128 * ASTR;
        #pragma unroll
        for (int kk = 0; kk < KC; kk += 8) {
            uint32_t af[4][4], bf[4][2];
            #pragma unroll
            for (int mt = 0; mt < 4; mt++) {
                int row = mW + mt * 16 + g;
                af[mt][0] = Ab[row * ASTR + kk + tg];
                af[mt][1] = Ab[(row + 8) * ASTR + kk + tg];
                af[mt][2] = Ab[row * ASTR + kk + tg + 4];
                af[mt][3] = Ab[(row + 8) * ASTR + kk + tg + 4];
            }
            #pragma unroll
            for (int nt = 0; nt < 4; nt++) {
                int col = nW + nt * 8 + g;
                bf[nt][0] = Bbuf[col * ASTR + kk + tg];
                bf[nt][1] = Bbuf[col * ASTR + kk + tg + 4];
            }
            #pragma unroll
            for (int mt = 0; mt < 4; mt++)
                #pragma unroll
                for (int nt = 0; nt < 4; nt++)
                    mma_tf32(acc[mt][nt], af[mt][0], af[mt][1], af[mt][2], af[mt][3],
                             bf[nt][0], bf[nt][1]);
        }

        if (more) {
            uint32_t* Ad = As + (buf ^ 1) * 128 * ASTR;
            uint32_t* Bd = Bs + (buf ^ 1) * 128 * ASTR;
            #pragma unroll
            for (int q = 0; q < 4; q++) {
                int k = 16 * kh + 4 * q;
                uint4 ua = make_uint4(f2tf(ra[q].x), f2tf(ra[q].y), f2tf(ra[q].z), f2tf(ra[q].w));
                uint4 ub = make_uint4(f2tf(rb[q].x), f2tf(rb[q].y), f2tf(rb[q].z), f2tf(rb[q].w));
                *(uint4*)(Ad + sm * ASTR + k) = ua;
                *(uint4*)(Bd + sm * ASTR + k) = ub;
            }
        }
        __syncthreads();
        buf ^= 1;
    }

    // epilogue: bias + store (float2, cols 2t/2t+1 contiguous)
    #pragma unroll
    for (int mt = 0; mt < 4; mt++) {
        int r0 = bm * 128 + mW + mt * 16 + g;
        #pragma unroll
        for (int nt = 0; nt < 4; nt++) {
            int c = bn * 128 + nW + nt * 8 + 2 * tg;
            *(float2*)(g_xproj + (size_t)r0 * GG + c) =
                make_float2(acc[mt][nt][0] + bb[nt][0], acc[mt][nt][1] + bb[nt][1]);
            *(float2*)(g_xproj + (size_t)(r0 + 8) * GG + c) =
                make_float2(acc[mt][nt][2] + bb[nt][0], acc[mt][nt][3] + bb[nt][1]);
        }
    }
}

// ---------------------------------------------------------------------------
// Persistent recurrence kernel (tf32 tensor cores).
// 256 blocks = 64 n-tiles (N=64) x 4 k-splits (K=256 each).
// W tile (64x256, tf32) cached in SMEM for the whole layer.
// Per step: stage h half-chunks, MMA into 64x64 partials, barrier,
// elementwise phase B (c in register), barrier.
// ---------------------------------------------------------------------------
#define WSTR 260
#define HSTR 132

__global__ void __launch_bounds__(256, 2) rec_persist_tc_kernel(
    const float* __restrict__ Whh,
    float* __restrict__ out_ext,
    int out_is_hbuf)
{
    extern __shared__ uint32_t smw[];
    uint32_t* Ws = smw;                 // [64][260] tf32 W tile (persistent)
    uint32_t* Hs = smw + 64 * WSTR;     // [64][132] tf32 h half-chunk

    const int tid  = threadIdx.x;
    const int bn   = blockIdx.x & 63;
    const int ks   = blockIdx.x >> 6;
    const int kbase = ks * (HH / KSPLIT);

    const int lane = tid & 31, wid = tid >> 5;
    const int g    = lane >> 2, tg = lane & 3;
    const int wm   = wid >> 1;          // 0..3 -> 16 rows
    const int wn   = wid & 1;           // 0..1 -> 32 cols
    const int mW   = wm * 16, nW = wn * 32;

    // Load W tile into SMEM once (tf32-packed)
    {
        int n = tid & 63, cq = tid >> 6;
        const float* Wg = Whh + (size_t)(bn * 64 + n) * HH + kbase;
        #pragma unroll 4
        for (int q = 0; q < 16; q++) {
            int k = 4 * (cq + 4 * q);
            float4 v = *(const float4*)(Wg + k);
            uint4 u = make_uint4(f2tf(v.x), f2tf(v.y), f2tf(v.z), f2tf(v.w));
            *(uint4*)(Ws + n * WSTR + k) = u;
        }
    }
    __syncthreads();

    // elementwise mapping
    const int eidx = blockIdx.x * 256 + tid;
    const int b = eidx >> 10;
    const int j = eidx & 1023;
    const float* xp_base = g_xproj + (size_t)b * TT * GG + j;
    float* out = out_is_hbuf ? g_hbuf : out_ext;
    float* out_base = out + (size_t)b * TT * HH + j;
    float creg = 0.0f;

    float* Pout = g_part + (size_t)ks * BB * GG + (size_t)bn * 64;

    for (int t = 0; t < TT; t++) {
        if (t > 0) {
            float acc[4][4];
            #pragma unroll
            for (int nt = 0; nt < 4; nt++)
                #pragma unroll
                for (int e = 0; e < 4; e++) acc[nt][e] = 0.f;

            #pragma unroll
            for (int half = 0; half < 2; half++) {
                // stage h chunk [64][128] -> Hs
                {
                    int m = tid & 63, cq = tid >> 6;
                    const float* Hg = g_h + (size_t)m * HH + kbase + half * 128;
                    float4 rv[8];
                    #pragma unroll
                    for (int q = 0; q < 8; q++)
                        rv[q] = *(const float4*)(Hg + 4 * (cq + 4 * q));
                    #pragma unroll
                    for (int q = 0; q < 8; q++) {
                        int k = 4 * (cq + 4 * q);
                        uint4 u = make_uint4(f2tf(rv[q].x), f2tf(rv[q].y),
                                             f2tf(rv[q].z), f2tf(rv[q].w));
                        *(uint4*)(Hs + m * HSTR + k) = u;
                    }
                }
                __syncthreads();

                #pragma unroll
                for (int kk = 0; kk < 128; kk += 8) {
                    uint32_t a0 = Hs[(mW + g) * HSTR + kk + tg];
                    uint32_t a1 = Hs[(mW + g + 8) * HSTR + kk + tg];
                    uint32_t a2 = Hs[(mW + g) * HSTR + kk + tg + 4];
                    uint32_t a3 = Hs[(mW + g + 8) * HSTR + kk + tg + 4];
                    #pragma unroll
                    for (int nt = 0; nt < 4; nt++) {
                        int col = nW + nt * 8 + g;
                        uint32_t b0 = Ws[col * WSTR + half * 128 + kk + tg];
                        uint32_t b1 = Ws[col * WSTR + half * 128 + kk + tg + 4];
                        mma_tf32(acc[nt], a0, a1, a2, a3, b0, b1);
                    }
                }
                __syncthreads();
            }

            // write partials
            #pragma unroll
            for (int nt = 0; nt < 4; nt++) {
                int c = nW + nt * 8 + 2 * tg;
                *(float2*)(Pout + (size_t)(mW + g) * GG + c) =
                    make_float2(acc[nt][0], acc[nt][1]);
                *(float2*)(Pout + (size_t)(mW + g + 8) * GG + c) =
                    make_float2(acc[nt][2], acc[nt][3]);
            }
        }

        grid_barrier();   // partials visible

        // phase B: elementwise LSTM update
        {
            const float* xp = xp_base + (size_t)t * GG;
            float gi = xp[0];
            float gf = xp[HH];
            float gg = xp[2 * HH];
            float go = xp[3 * HH];

            if (t > 0) {
                size_t pb = (size_t)b * GG + j;
                #pragma unroll
                for (int s = 0; s < KSPLIT; s++) {
                    const float* P = g_part + (size_t)s * BB * GG + pb;
                    gi += P[0];
                    gf += P[HH];
                    gg += P[2 * HH];
                    go += P[3 * HH];
                }
            }

            float i_g = 1.f / (1.f + expf(-gi));
            float f_g = 1.f / (1.f + expf(-gf));
            float g_g = tanhf(gg);
            float o_g = 1.f / (1.f + expf(-go));

            creg = f_g * creg + i_g * g_g;
            float h = o_g * tanhf(creg);

            g_h[eidx] = h;
            out_base[(size_t)t * HH] = h;
        }

        grid_barrier();   // h visible before next step's GEMM
    }
}

// ---------------------------------------------------------------------------
extern "C" void kernel_launch(void* const* d_in, const int* in_sizes, int n_in,
                              void* d_out, int out_size)
{
    const float* x   = (const float*)d_in[0];   // [B, T, I]
    const float* Wih = (const float*)d_in[1];   // [L, 4H, I]
    const float* Whh = (const float*)d_in[2];   // [L, 4H, H]
    const float* bih = (const float*)d_in[3];   // [L, 4H]
    const float* bhh = (const float*)d_in[4];   // [L, 4H]
    float* out = (float*)d_out;                 // [B, T, H]

    const int gemm_smem = 4 * 128 * ASTR * 4;               // 73728 B
    const int rec_smem  = (64 * WSTR + 64 * HSTR) * 4;      // 100352 B
    cudaFuncSetAttribute(gemm_bias_tc_kernel,
                         cudaFuncAttributeMaxDynamicSharedMemorySize, gemm_smem);
    cudaFuncSetAttribute(rec_persist_tc_kernel,
                         cudaFuncAttributeMaxDynamicSharedMemorySize, rec_smem);

    for (int l = 0; l < 3; l++) {
        const float* Wih_l = Wih + (size_t)l * GG * II;
        const float* Whh_l = Whh + (size_t)l * GG * HH;
        const float* bih_l = bih + (size_t)l * GG;
        const float* bhh_l = bhh + (size_t)l * GG;

        int in_is_hbuf  = (l != 0);
        int out_is_hbuf = (l != 2);

        dim3 g1(GG / 128, MM / 128);   // (32, 256)
        gemm_bias_tc_kernel<<<g1, 256, gemm_smem>>>(x, Wih_l, bih_l, bhh_l, in_is_hbuf);

        rec_persist_tc_kernel<<<NBLK, 256, rec_smem>>>(Whh_l, out, out_is_hbuf);
    }
}

// round 6
// speedup vs baseline: 1.8329x; 1.0193x over previous
#include <cuda_runtime.h>
#include <math.h>
#include <stdint.h>

#define BB 64
#define TT 512
#define II 1024
#define HH 1024
#define GG 4096              // 4*H
#define MM (BB*TT)           // 32768
#define KSPLIT 4
#define NBLK 256             // persistent kernel grid size

// Scratch (device globals: allocation-free per harness rules)
__device__ float g_xproj[(size_t)MM * GG];          // [B*T, 4H]  512 MB
__device__ float g_hbuf [(size_t)MM * HH];          // [B, T, H]  128 MB
__device__ float g_h    [BB * HH];                  // current h
__device__ float g_part [(size_t)KSPLIT * BB * GG]; // split-K partials, 4 MB

// Software grid barrier state (zero-initialized)
__device__ unsigned g_bar_count;
__device__ volatile unsigned g_bar_gen;

__device__ __forceinline__ void grid_barrier()
{
    __syncthreads();
    if (threadIdx.x == 0) {
        unsigned gen = g_bar_gen;
        __threadfence();
        unsigned prev = atomicAdd(&g_bar_count, 1u);
        if (prev == NBLK - 1) {
            atomicExch(&g_bar_count, 0u);
            __threadfence();
            g_bar_gen = gen + 1;
        } else {
            while (g_bar_gen == gen) { }
            __threadfence();
        }
    }
    __syncthreads();
}

// ---------------------------------------------------------------------------
// tf32 / cp.async helpers
// ---------------------------------------------------------------------------
__device__ __forceinline__ uint32_t f2tf(float f)
{
    uint32_t u;
    asm("cvt.rna.tf32.f32 %0, %1;" : "=r"(u) : "f"(f));
    return u;
}

__device__ __forceinline__ void mma_tf32(float* d,
    uint32_t a0, uint32_t a1, uint32_t a2, uint32_t a3,
    uint32_t b0, uint32_t b1)
{
    asm("mma.sync.aligned.m16n8k8.row.col.f32.tf32.tf32.f32 "
        "{%0,%1,%2,%3}, {%4,%5,%6,%7}, {%8,%9}, {%0,%1,%2,%3};"
        : "+f"(d[0]), "+f"(d[1]), "+f"(d[2]), "+f"(d[3])
        : "r"(a0), "r"(a1), "r"(a2), "r"(a3), "r"(b0), "r"(b1));
}

__device__ __forceinline__ void cp_async16_ca(uint32_t saddr, const void* g)
{
    asm volatile("cp.async.ca.shared.global [%0], [%1], 16;" :: "r"(saddr), "l"(g));
}
__device__ __forceinline__ void cp_async16_cg(uint32_t saddr, const void* g)
{
    asm volatile("cp.async.cg.shared.global [%0], [%1], 16;" :: "r"(saddr), "l"(g));
}
__device__ __forceinline__ void cp_commit() { asm volatile("cp.async.commit_group;"); }
template<int N>
__device__ __forceinline__ void cp_wait() { asm volatile("cp.async.wait_group %0;" :: "n"(N)); }

// ---------------------------------------------------------------------------
// Input-projection GEMM (tf32 tensor cores, cp.async staging of raw fp32):
//   xproj[m,n] = sum_k A[m,k]*W[n,k] + bih[n] + bhh[n]
// Tile 128x128, k-chunks of 32, double-buffered SMEM stride-36 rows.
// 8 warps in 2(m)x4(n), warp tile 64x32. tf32 conversion at fragment load.
// ---------------------------------------------------------------------------
#define KC 32
#define ASTR 36

__global__ void __launch_bounds__(256, 2) gemm_bias_tc_kernel(
    const float* __restrict__ Ain,
    const float* __restrict__ W,
    const float* __restrict__ bih,
    const float* __restrict__ bhh,
    int in_is_hbuf)
{
    extern __shared__ float smf[];
    float* As = smf;                       // [2][128][36] raw fp32
    float* Bs = smf + 2 * 128 * ASTR;      // [2][128][36]

    const float* A = in_is_hbuf ? (const float*)g_hbuf : Ain;

    const int tid  = threadIdx.x;
    const int bn   = blockIdx.x;             // 0..31
    const int bm   = blockIdx.y;             // 0..255
    const int lane = tid & 31, wid = tid >> 5;
    const int g    = lane >> 2, tg = lane & 3;
    const int wm   = wid >> 2;               // 0..1
    const int wn   = wid & 3;                // 0..3
    const int mW   = wm * 64, nW = wn * 32;

    // staging map: row sm, k-half kh (16 floats per thread per matrix)
    const int sm = tid & 127;
    const int kh = tid >> 7;                 // 0/1

    const float* Ag = A + (size_t)(bm * 128 + sm) * II + 16 * kh;
    const float* Wg = W + (size_t)(bn * 128 + sm) * II + 16 * kh;

    const uint32_t sA = (uint32_t)__cvta_generic_to_shared(As + sm * ASTR + 16 * kh);
    const uint32_t sB = (uint32_t)__cvta_generic_to_shared(Bs + sm * ASTR + 16 * kh);
    const uint32_t bufStride = 128 * ASTR * 4;   // bytes per buffer

    float acc[4][4][4];
    #pragma unroll
    for (int mt = 0; mt < 4; mt++)
        #pragma unroll
        for (int nt = 0; nt < 4; nt++)
            #pragma unroll
            for (int e = 0; e < 4; e++) acc[mt][nt][e] = 0.f;

    float bb[4][2];
    #pragma unroll
    for (int nt = 0; nt < 4; nt++)
        #pragma unroll
        for (int e = 0; e < 2; e++) {
            int n = bn * 128 + nW + nt * 8 + 2 * tg + e;
            bb[nt][e] = bih[n] + bhh[n];
        }

    // prologue: prefetch chunk 0 into buf 0
    #pragma unroll
    for (int q = 0; q < 4; q++) {
        cp_async16_ca(sA + q * 16, Ag + 4 * q);
        cp_async16_ca(sB + q * 16, Wg + 4 * q);
    }
    cp_commit();

    int buf = 0;
    for (int k0 = 0; k0 < II; k0 += KC) {
        const bool more = (k0 + KC) < II;
        if (more) {
            uint32_t dA = sA + (buf ^ 1) * bufStride;
            uint32_t dB = sB + (buf ^ 1) * bufStride;
            #pragma unroll
            for (int q = 0; q < 4; q++) {
                cp_async16_ca(dA + q * 16, Ag + k0 + KC + 4 * q);
                cp_async16_ca(dB + q * 16, Wg + k0 + KC + 4 * q);
            }
            cp_commit();
            cp_wait<1>();
        } else {
            cp_wait<0>();
        }
        __syncthreads();

        const float* Ab   = As + buf * 128 * ASTR;
        const float* Bbuf = Bs + buf * 128 * ASTR;
        #pragma unroll
        for (int kk = 0; kk < KC; kk += 8) {
            uint32_t af[4][4], bf[4][2];
            #pragma unroll
            for (int mt = 0; mt < 4; mt++) {
                int row = mW + mt * 16 + g;
                af[mt][0] = f2tf(Ab[row * ASTR + kk + tg]);
                af[mt][1] = f2tf(Ab[(row + 8) * ASTR + kk + tg]);
                af[mt][2] = f2tf(Ab[row * ASTR + kk + tg + 4]);
                af[mt][3] = f2tf(Ab[(row + 8) * ASTR + kk + tg + 4]);
            }
            #pragma unroll
            for (int nt = 0; nt < 4; nt++) {
                int col = nW + nt * 8 + g;
                bf[nt][0] = f2tf(Bbuf[col * ASTR + kk + tg]);
                bf[nt][1] = f2tf(Bbuf[col * ASTR + kk + tg + 4]);
            }
            #pragma unroll
            for (int mt = 0; mt < 4; mt++)
                #pragma unroll
                for (int nt = 0; nt < 4; nt++)
                    mma_tf32(acc[mt][nt], af[mt][0], af[mt][1], af[mt][2], af[mt][3],
                             bf[nt][0], bf[nt][1]);
        }
        __syncthreads();   // all reads of buf done before next prefetch overwrites peer buf
        buf ^= 1;
    }

    // epilogue: bias + store
    #pragma unroll
    for (int mt = 0; mt < 4; mt++) {
        int r0 = bm * 128 + mW + mt * 16 + g;
        #pragma unroll
        for (int nt = 0; nt < 4; nt++) {
            int c = bn * 128 + nW + nt * 8 + 2 * tg;
            *(float2*)(g_xproj + (size_t)r0 * GG + c) =
                make_float2(acc[mt][nt][0] + bb[nt][0], acc[mt][nt][1] + bb[nt][1]);
            *(float2*)(g_xproj + (size_t)(r0 + 8) * GG + c) =
                make_float2(acc[mt][nt][2] + bb[nt][0], acc[mt][nt][3] + bb[nt][1]);
        }
    }
}

// ---------------------------------------------------------------------------
// Persistent recurrence kernel (tf32 tensor cores).
// 256 blocks = 64 n-tiles x 4 k-splits (K=256 each).
// W tile (64x256, tf32-converted) cached in SMEM for the whole layer.
// h chunks staged raw fp32 via cp.async.cg (L2 path), tf32 cvt at frag load.
// ---------------------------------------------------------------------------
#define WSTR 260
#define HSTR 132

__global__ void __launch_bounds__(256, 2) rec_persist_tc_kernel(
    const float* __restrict__ Whh,
    float* __restrict__ out_ext,
    int out_is_hbuf)
{
    extern __shared__ float smf[];
    uint32_t* Ws = (uint32_t*)smf;           // [64][260] tf32 W tile (persistent)
    float*    Hs = smf + 64 * WSTR;          // [64][132] raw fp32 h half-chunk

    const int tid  = threadIdx.x;
    const int bn   = blockIdx.x & 63;
    const int ks   = blockIdx.x >> 6;
    const int kbase = ks * (HH / KSPLIT);

    const int lane = tid & 31, wid = tid >> 5;
    const int g    = lane >> 2, tg = lane & 3;
    const int wm   = wid >> 1;               // 0..3 -> 16 rows
    const int wn   = wid & 1;                // 0..1 -> 32 cols
    const int mW   = wm * 16, nW = wn * 32;

    // Load W tile into SMEM once (tf32-packed)
    {
        int n = tid & 63, cq = tid >> 6;
        const float* Wg = Whh + (size_t)(bn * 64 + n) * HH + kbase;
        for (int q = 0; q < 16; q += 2) {
            int k0 = 4 * (cq + 4 * q);
            int k1 = 4 * (cq + 4 * (q + 1));
            float4 v0 = *(const float4*)(Wg + k0);
            float4 v1 = *(const float4*)(Wg + k1);
            *(uint4*)(Ws + n * WSTR + k0) =
                make_uint4(f2tf(v0.x), f2tf(v0.y), f2tf(v0.z), f2tf(v0.w));
            *(uint4*)(Ws + n * WSTR + k1) =
                make_uint4(f2tf(v1.x), f2tf(v1.y), f2tf(v1.z), f2tf(v1.w));
        }
    }
    __syncthreads();

    // h staging map: row m, col group cq -> 8x 16B cp.async per half
    const int m_st = tid & 63;
    const int cq   = tid >> 6;               // 0..3
    const uint32_t sH = (uint32_t)__cvta_generic_to_shared(Hs + m_st * HSTR);

    // elementwise mapping
    const int eidx = blockIdx.x * 256 + tid;
    const int b = eidx >> 10;
    const int j = eidx & 1023;
    const float* xp_base = g_xproj + (size_t)b * TT * GG + j;
    float* out = out_is_hbuf ? g_hbuf : out_ext;
    float* out_base = out + (size_t)b * TT * HH + j;
    float creg = 0.0f;

    float* Pout = g_part + (size_t)ks * BB * GG + (size_t)bn * 64;

    for (int t = 0; t < TT; t++) {
        if (t > 0) {
            float acc[4][4];
            #pragma unroll
            for (int nt = 0; nt < 4; nt++)
                #pragma unroll
                for (int e = 0; e < 4; e++) acc[nt][e] = 0.f;

            #pragma unroll
            for (int half = 0; half < 2; half++) {
                // stage h chunk [64][128] -> Hs (raw fp32, L2 path)
                {
                    const float* Hg = g_h + (size_t)m_st * HH + kbase + half * 128;
                    #pragma unroll
                    for (int q = 0; q < 8; q++) {
                        int k = 4 * (cq + 4 * q);
                        cp_async16_cg(sH + k * 4, Hg + k);
                    }
                    cp_commit();
                    cp_wait<0>();
                }
                __syncthreads();

                #pragma unroll
                for (int kk = 0; kk < 128; kk += 8) {
                    uint32_t a0 = f2tf(Hs[(mW + g) * HSTR + kk + tg]);
                    uint32_t a1 = f2tf(Hs[(mW + g + 8) * HSTR + kk + tg]);
                    uint32_t a2 = f2tf(Hs[(mW + g) * HSTR + kk + tg + 4]);
                    uint32_t a3 = f2tf(Hs[(mW + g + 8) * HSTR + kk + tg + 4]);
                    #pragma unroll
                    for (int nt = 0; nt < 4; nt++) {
                        int col = nW + nt * 8 + g;
                        uint32_t b0 = Ws[col * WSTR + half * 128 + kk + tg];
                        uint32_t b1 = Ws[col * WSTR + half * 128 + kk + tg + 4];
                        mma_tf32(acc[nt], a0, a1, a2, a3, b0, b1);
                    }
                }
                __syncthreads();
            }

            // write partials
            #pragma unroll
            for (int nt = 0; nt < 4; nt++) {
                int c = nW + nt * 8 + 2 * tg;
                *(float2*)(Pout + (size_t)(mW + g) * GG + c) =
                    make_float2(acc[nt][0], acc[nt][1]);
                *(float2*)(Pout + (size_t)(mW + g + 8) * GG + c) =
                    make_float2(acc[nt][2], acc[nt][3]);
            }
        }

        grid_barrier();   // partials visible

        // phase B: elementwise LSTM update
        {
            const float* xp = xp_base + (size_t)t * GG;
            float gi = xp[0];
            float gf = xp[HH];
            float gg = xp[2 * HH];
            float go = xp[3 * HH];

            if (t > 0) {
                size_t pb = (size_t)b * GG + j;
                #pragma unroll
                for (int s = 0; s < KSPLIT; s++) {
                    const float* P = g_part + (size_t)s * BB * GG + pb;
                    gi += P[0];
                    gf += P[HH];
                    gg += P[2 * HH];
                    go += P[3 * HH];
                }
            }

            float i_g = 1.f / (1.f + expf(-gi));
            float f_g = 1.f / (1.f + expf(-gf));
            float g_g = tanhf(gg);
            float o_g = 1.f / (1.f + expf(-go));

            creg = f_g * creg + i_g * g_g;
            float h = o_g * tanhf(creg);

            g_h[eidx] = h;
            out_base[(size_t)t * HH] = h;
        }

        grid_barrier();   // h visible before next step's GEMM
    }
}

// ---------------------------------------------------------------------------
extern "C" void kernel_launch(void* const* d_in, const int* in_sizes, int n_in,
                              void* d_out, int out_size)
{
    const float* x   = (const float*)d_in[0];   // [B, T, I]
    const float* Wih = (const float*)d_in[1];   // [L, 4H, I]
    const float* Whh = (const float*)d_in[2];   // [L, 4H, H]
    const float* bih = (const float*)d_in[3];   // [L, 4H]
    const float* bhh = (const float*)d_in[4];   // [L, 4H]
    float* out = (float*)d_out;                 // [B, T, H]

    const int gemm_smem = 4 * 128 * ASTR * 4;               // 73728 B
    const int rec_smem  = (64 * WSTR + 64 * HSTR) * 4;      // 100352 B
    cudaFuncSetAttribute(gemm_bias_tc_kernel,
                         cudaFuncAttributeMaxDynamicSharedMemorySize, gemm_smem);
    cudaFuncSetAttribute(rec_persist_tc_kernel,
                         cudaFuncAttributeMaxDynamicSharedMemorySize, rec_smem);

    for (int l = 0; l < 3; l++) {
        const float* Wih_l = Wih + (size_t)l * GG * II;
        const float* Whh_l = Whh + (size_t)l * GG * HH;
        const float* bih_l = bih + (size_t)l * GG;
        const float* bhh_l = bhh + (size_t)l * GG;

        int in_is_hbuf  = (l != 0);
        int out_is_hbuf = (l != 2);

        dim3 g1(GG / 128, MM / 128);   // (32, 256)
        gemm_bias_tc_kernel<<<g1, 256, gemm_smem>>>(x, Wih_l, bih_l, bhh_l, in_is_hbuf);

        rec_persist_tc_kernel<<<NBLK, 256, rec_smem>>>(Whh_l, out, out_is_hbuf);
    }
}